// round 5
// baseline (speedup 1.0000x reference)
#include <cuda_runtime.h>
#include <math.h>

// PDHG / Chambolle-Pock TV denoising, persistent-kernel formulation.
// P=2, C=1, NX=128, NY=128, NT=8; T=128 iterations.
// One thread per (p,x,y) pencil of NT=8 t-values; x0,p,q2,xnoisy,lambda in regs.
// xbar,q0,q1 double-buffered in __device__ globals for halo exchange.
// Grid barrier = DISTRIBUTED per-CTA release flags + vectorized acquire polling
// (no shared atomic counter -> no per-address L2 atomic serialization).

#define NXD 128
#define NYD 128
#define NTD 8
#define NPB 2
#define NPIX (NPB * NXD * NYD * NTD)   // 262144
#define NCTA 128
#define NTHR 256

__device__ __align__(256) float g_xbar[2][NPIX];
__device__ __align__(256) float g_q0[2][NPIX];
__device__ __align__(256) float g_q1[2][NPIX];
__device__ __align__(512) unsigned g_flags[NCTA];   // per-CTA monotonic epoch

// ---- memory-model primitives ----
__device__ __forceinline__ void st_release_gpu(unsigned* p, unsigned v) {
    asm volatile("st.release.gpu.global.u32 [%0], %1;" :: "l"(p), "r"(v) : "memory");
}
__device__ __forceinline__ unsigned ld_acquire_gpu(const unsigned* p) {
    unsigned v;
    asm volatile("ld.acquire.gpu.global.u32 %0, [%1];" : "=r"(v) : "l"(p) : "memory");
    return v;
}
__device__ __forceinline__ uint4 ld_acquire_gpu_v4(const unsigned* p) {
    uint4 v;
    asm volatile("ld.acquire.gpu.global.v4.u32 {%0,%1,%2,%3}, [%4];"
                 : "=r"(v.x), "=r"(v.y), "=r"(v.z), "=r"(v.w) : "l"(p) : "memory");
    return v;
}

// Halo loads: L2-only (.cg) -> never sees stale L1.
#define LOADP_CG(dst, ptr, off) do { \
    float4 a_ = __ldcg(reinterpret_cast<const float4*>((ptr) + (off))); \
    float4 b_ = __ldcg(reinterpret_cast<const float4*>((ptr) + (off) + 4)); \
    dst[0]=a_.x; dst[1]=a_.y; dst[2]=a_.z; dst[3]=a_.w; \
    dst[4]=b_.x; dst[5]=b_.y; dst[6]=b_.z; dst[7]=b_.w; } while(0)

#define LOADP(dst, ptr, off) do { \
    float4 a_ = *reinterpret_cast<const float4*>((ptr) + (off)); \
    float4 b_ = *reinterpret_cast<const float4*>((ptr) + (off) + 4); \
    dst[0]=a_.x; dst[1]=a_.y; dst[2]=a_.z; dst[3]=a_.w; \
    dst[4]=b_.x; dst[5]=b_.y; dst[6]=b_.z; dst[7]=b_.w; } while(0)

#define STOREP(ptr, off, src) do { \
    *reinterpret_cast<float4*>((ptr) + (off))     = make_float4(src[0],src[1],src[2],src[3]); \
    *reinterpret_cast<float4*>((ptr) + (off) + 4) = make_float4(src[4],src[5],src[6],src[7]); } while(0)

// Distributed grid barrier.
// Arrival: one st.release.gpu to this CTA's own flag (128 distinct addresses,
// fully parallel -- avoids the ~27cyc/op single-address L2 atomic serialization).
// Wait: warp 0 polls all 128 flags, 4 per lane via ld.acquire.gpu.v4.
// base = this CTA's own flag at entry (only this CTA writes it -> race-free read;
// all flags equal at quiescence; unsigned-diff compare is wrap-safe).
__device__ __forceinline__ void grid_barrier(unsigned base, unsigned e) {
    __syncthreads();
    if (threadIdx.x < 32) {
        if (threadIdx.x == 0) st_release_gpu(&g_flags[blockIdx.x], base + e);
        const unsigned lane = threadIdx.x;
        bool ok;
        do {
            uint4 v = ld_acquire_gpu_v4(&g_flags[lane << 2]);
            ok = (v.x - base >= e) && (v.y - base >= e) &&
                 (v.z - base >= e) && (v.w - base >= e);
        } while (!__all_sync(0xffffffffu, ok));
    }
    __syncthreads();
}

extern "C" __global__ void __launch_bounds__(NTHR, 1)
pdhg_persist_kernel(const float* __restrict__ xin,
                    const float* __restrict__ lamin,
                    const float* __restrict__ taup,
                    const float* __restrict__ sigp,
                    const float* __restrict__ thp,
                    const int*   __restrict__ Tp,
                    float* __restrict__ out)
{
    // ---- scalars ----
    const float L    = sqrtf(13.0f);
    const float sig  = (1.0f / (1.0f + expf(-sigp[0]))) / L;
    const float tauv = (1.0f / (1.0f + expf(-taup[0]))) / L;
    const float th   = 1.0f / (1.0f + expf(-thp[0]));
    const float i1s  = 1.0f / (1.0f + sig);

    int T = Tp[0];
    if (T < 1 || T > 65536) {
        float tf = __int_as_float(T);
        T = (int)tf;
        if (T < 1 || T > 65536) T = 128;
    }

    // barrier base epoch: this CTA's own flag (only we write it -> no race).
    const unsigned base = ld_acquire_gpu(&g_flags[blockIdx.x]);

    // ---- thread -> pencil mapping: CTA = 16x16 (x,y) tile ----
    const int cta  = blockIdx.x;          // 0..127
    const int pp   = cta >> 6;            // batch 0..1
    const int tile = cta & 63;            // 8x8 tiles of 16x16
    const int x = ((tile >> 3) << 4) + (threadIdx.x >> 4);
    const int y = ((tile & 7)  << 4) + (threadIdx.x & 15);
    const int xp = (x + 1) & 127, xm = (x - 1) & 127;
    const int yp = (y + 1) & 127, ym = (y - 1) & 127;

    const int pb  = pp << 14;
    const int o   = (pb + (x  << 7) + y ) << 3;
    const int opx = (pb + (xp << 7) + y ) << 3;
    const int omx = (pb + (xm << 7) + y ) << 3;
    const int opy = (pb + (x  << 7) + yp) << 3;
    const int omy = (pb + (x  << 7) + ym) << 3;

    // ---- persistent register state ----
    float xn[8], x0[8], pv[8], q0[8], q1[8], q2[8], xb[8], lam[8], lmx[8], lmy[8];
    LOADP(xn,  xin,   o);
    LOADP(lam, lamin, o);
    LOADP(lmx, lamin, omx);
    LOADP(lmy, lamin, omy);
#pragma unroll
    for (int t = 0; t < 8; t++) {
        x0[t] = xn[t]; pv[t] = xn[t]; xb[t] = xn[t];
        q0[t] = 0.0f;  q1[t] = 0.0f;  q2[t] = 0.0f;
    }

    // init shared buffers (buffer 0 is "cur" for iteration 0)
    STOREP(g_xbar[0], o, xb);
    {
        float zz[8] = {0.f,0.f,0.f,0.f,0.f,0.f,0.f,0.f};
        STOREP(g_q0[0], o, zz);
        STOREP(g_q1[0], o, zz);
    }

    grid_barrier(base, 1);

    // ---- main PDHG loop ----
    for (int it = 0; it < T; ++it) {
        const int cur = it & 1;
        const int nxt = cur ^ 1;

        // front-batch all halo loads (MLP=6), .cg = fresh from L2
        float bpx[8], bmx[8], bpy[8], bmy[8], qa[8], qb[8];
        LOADP_CG(bpx, g_xbar[cur], opx);
        LOADP_CG(bmx, g_xbar[cur], omx);
        LOADP_CG(bpy, g_xbar[cur], opy);
        LOADP_CG(bmy, g_xbar[cur], omy);
        LOADP_CG(qa,  g_q0[cur],   omx);   // q0 state at (x-1, y)
        LOADP_CG(qb,  g_q1[cur],   omy);   // q1 state at (x, y-1)

        // t-direction dual (periodic fwd diff) — overlaps halo-load latency
        float q2n[8];
#pragma unroll
        for (int t = 0; t < 8; t++) {
            float v = q2[t] + sig * (xb[(t + 1) & 7] - xb[t]);
            q2n[t] = fminf(fmaxf(v, -lam[t]), lam[t]);
        }

#pragma unroll
        for (int t = 0; t < 8; t++) {
            float pn = (pv[t] + sig * (xb[t] - xn[t])) * i1s;

            float v0  = q0[t] + sig * (bpx[t] - xb[t]);
            float q0n = fminf(fmaxf(v0, -lam[t]), lam[t]);
            float v1  = q1[t] + sig * (bpy[t] - xb[t]);
            float q1n = fminf(fmaxf(v1, -lam[t]), lam[t]);

            // redundant recompute of neighbor duals for the divergence
            float v0m = qa[t] + sig * (xb[t] - bmx[t]);
            float q0m = fminf(fmaxf(v0m, -lmx[t]), lmx[t]);
            float v1m = qb[t] + sig * (xb[t] - bmy[t]);
            float q1m = fminf(fmaxf(v1m, -lmy[t]), lmy[t]);

            float dv = (q0m - q0n) + (q1m - q1n)
                     + (q2n[(t + 7) & 7] - q2n[t]);

            float x1  = x0[t] - tauv * (pn + dv);
            float xbn = x1 + th * (x1 - x0[t]);

            x0[t] = x1; pv[t] = pn; q0[t] = q0n; q1[t] = q1n; xb[t] = xbn;
        }
#pragma unroll
        for (int t = 0; t < 8; t++) q2[t] = q2n[t];

        if (it != T - 1) {
            STOREP(g_xbar[nxt], o, xb);
            STOREP(g_q0[nxt],   o, q0);
            STOREP(g_q1[nxt],   o, q1);
            grid_barrier(base, it + 2);
        }
    }

    // ---- output ----
    STOREP(out, o, x0);
}

extern "C" void kernel_launch(void* const* d_in, const int* in_sizes, int n_in,
                              void* d_out, int out_size) {
    const float* x    = (const float*)d_in[0];
    const float* lam  = (const float*)d_in[1];
    const float* tau  = (const float*)d_in[2];
    const float* sigm = (const float*)d_in[3];
    const float* thet = (const float*)d_in[4];
    const int*   Tp   = (const int*)d_in[5];
    float* out = (float*)d_out;
    pdhg_persist_kernel<<<NCTA, NTHR>>>(x, lam, tau, sigm, thet, Tp, out);
}

// round 6
// speedup vs baseline: 2.9534x; 2.9534x over previous
#include <cuda_runtime.h>
#include <math.h>

// PDHG / Chambolle-Pock TV denoising, persistent-kernel formulation.
// P=2, C=1, NX=128, NY=128, NT=8; T=128 iterations.
// One thread per (p,x,y) pencil of NT=8 t-values; x0,p,q2,xnoisy,lambda in regs.
// xbar,q0,q1 double-buffered in __device__ globals for halo exchange.
// Grid barrier = 2-level atomic tree (8 leaf counters -> 1 root counter) +
// single-word tid0 load-spin. Counters self-reset at kernel exit.

#define NXD 128
#define NYD 128
#define NTD 8
#define NPB 2
#define NPIX (NPB * NXD * NYD * NTD)   // 262144
#define NCTA 128
#define NTHR 256
#define NLEAF 8
#define CTAS_PER_LEAF (NCTA / NLEAF)   // 16

__device__ __align__(256) float g_xbar[2][NPIX];
__device__ __align__(256) float g_q0[2][NPIX];
__device__ __align__(256) float g_q1[2][NPIX];
// 8 leaf counters, 128 B apart (distinct L2 lines/slices), + 1 root counter.
__device__ __align__(128) unsigned g_leaf[NLEAF * 32];
__device__ __align__(128) unsigned g_root;

// ---- memory-model primitives ----
__device__ __forceinline__ unsigned atom_add_acqrel_gpu(unsigned* p, unsigned v) {
    unsigned old;
    asm volatile("atom.acq_rel.gpu.global.add.u32 %0, [%1], %2;"
                 : "=r"(old) : "l"(p), "r"(v) : "memory");
    return old;
}
__device__ __forceinline__ void st_release_gpu(unsigned* p, unsigned v) {
    asm volatile("st.release.gpu.global.u32 [%0], %1;" :: "l"(p), "r"(v) : "memory");
}
__device__ __forceinline__ unsigned ld_acquire_gpu(const unsigned* p) {
    unsigned v;
    asm volatile("ld.acquire.gpu.global.u32 %0, [%1];" : "=r"(v) : "l"(p) : "memory");
    return v;
}

// Halo loads: L2-only (.cg) -> never sees stale L1.
#define LOADP_CG(dst, ptr, off) do { \
    float4 a_ = __ldcg(reinterpret_cast<const float4*>((ptr) + (off))); \
    float4 b_ = __ldcg(reinterpret_cast<const float4*>((ptr) + (off) + 4)); \
    dst[0]=a_.x; dst[1]=a_.y; dst[2]=a_.z; dst[3]=a_.w; \
    dst[4]=b_.x; dst[5]=b_.y; dst[6]=b_.z; dst[7]=b_.w; } while(0)

#define LOADP(dst, ptr, off) do { \
    float4 a_ = *reinterpret_cast<const float4*>((ptr) + (off)); \
    float4 b_ = *reinterpret_cast<const float4*>((ptr) + (off) + 4); \
    dst[0]=a_.x; dst[1]=a_.y; dst[2]=a_.z; dst[3]=a_.w; \
    dst[4]=b_.x; dst[5]=b_.y; dst[6]=b_.z; dst[7]=b_.w; } while(0)

#define STOREP(ptr, off, src) do { \
    *reinterpret_cast<float4*>((ptr) + (off))     = make_float4(src[0],src[1],src[2],src[3]); \
    *reinterpret_cast<float4*>((ptr) + (off) + 4) = make_float4(src[4],src[5],src[6],src[7]); } while(0)

// 2-level grid barrier, epoch e = 1,2,... (counters start at 0 each run).
// Arrival: tid0 atomics its leaf (<=16 serialized per leaf, 8 leaves parallel);
// the 16th arriver of the leaf's epoch bumps the root. Release chain:
// leaf atom.acq_rel (orders this CTA's prior stores) -> root atom.acq_rel ->
// waiters' ld.acquire on root. Spin = ONE lane per CTA on ONE word (benign
// poll traffic; the R5 regression was 32-lane x 4-line polling storm).
__device__ __forceinline__ void grid_barrier(unsigned e) {
    __syncthreads();
    if (threadIdx.x == 0) {
        unsigned leaf = (blockIdx.x & (NLEAF - 1)) * 32u;
        unsigned old = atom_add_acqrel_gpu(&g_leaf[leaf], 1u);
        if ((old & (CTAS_PER_LEAF - 1u)) == CTAS_PER_LEAF - 1u) {
            atom_add_acqrel_gpu(&g_root, 1u);
        }
        while (ld_acquire_gpu(&g_root) < NLEAF * e) { }
    }
    __syncthreads();
}

extern "C" __global__ void __launch_bounds__(NTHR, 1)
pdhg_persist_kernel(const float* __restrict__ xin,
                    const float* __restrict__ lamin,
                    const float* __restrict__ taup,
                    const float* __restrict__ sigp,
                    const float* __restrict__ thp,
                    const int*   __restrict__ Tp,
                    float* __restrict__ out)
{
    // ---- scalars ----
    const float L    = sqrtf(13.0f);
    const float sig  = (1.0f / (1.0f + expf(-sigp[0]))) / L;
    const float tauv = (1.0f / (1.0f + expf(-taup[0]))) / L;
    const float th   = 1.0f / (1.0f + expf(-thp[0]));
    const float i1s  = 1.0f / (1.0f + sig);

    int T = Tp[0];
    if (T < 1 || T > 65536) {
        float tf = __int_as_float(T);
        T = (int)tf;
        if (T < 1 || T > 65536) T = 128;
    }

    // ---- thread -> pencil mapping: CTA = 16x16 (x,y) tile ----
    const int cta  = blockIdx.x;          // 0..127
    const int pp   = cta >> 6;            // batch 0..1
    const int tile = cta & 63;            // 8x8 tiles of 16x16
    const int x = ((tile >> 3) << 4) + (threadIdx.x >> 4);
    const int y = ((tile & 7)  << 4) + (threadIdx.x & 15);
    const int xp = (x + 1) & 127, xm = (x - 1) & 127;
    const int yp = (y + 1) & 127, ym = (y - 1) & 127;

    const int pb  = pp << 14;
    const int o   = (pb + (x  << 7) + y ) << 3;
    const int opx = (pb + (xp << 7) + y ) << 3;
    const int omx = (pb + (xm << 7) + y ) << 3;
    const int opy = (pb + (x  << 7) + yp) << 3;
    const int omy = (pb + (x  << 7) + ym) << 3;

    // ---- persistent register state ----
    float xn[8], x0[8], pv[8], q0[8], q1[8], q2[8], xb[8], lam[8], lmx[8], lmy[8];
    LOADP(xn,  xin,   o);
    LOADP(lam, lamin, o);
    LOADP(lmx, lamin, omx);
    LOADP(lmy, lamin, omy);
#pragma unroll
    for (int t = 0; t < 8; t++) {
        x0[t] = xn[t]; pv[t] = xn[t]; xb[t] = xn[t];
        q0[t] = 0.0f;  q1[t] = 0.0f;  q2[t] = 0.0f;
    }

    // init shared buffers (buffer 0 is "cur" for iteration 0)
    STOREP(g_xbar[0], o, xb);
    {
        float zz[8] = {0.f,0.f,0.f,0.f,0.f,0.f,0.f,0.f};
        STOREP(g_q0[0], o, zz);
        STOREP(g_q1[0], o, zz);
    }

    grid_barrier(1);

    // ---- main PDHG loop ----
    for (int it = 0; it < T; ++it) {
        const int cur = it & 1;
        const int nxt = cur ^ 1;

        // front-batch all halo loads (MLP=12), .cg = fresh from L2
        float bpx[8], bmx[8], bpy[8], bmy[8], qa[8], qb[8];
        LOADP_CG(bpx, g_xbar[cur], opx);
        LOADP_CG(bmx, g_xbar[cur], omx);
        LOADP_CG(bpy, g_xbar[cur], opy);
        LOADP_CG(bmy, g_xbar[cur], omy);
        LOADP_CG(qa,  g_q0[cur],   omx);   // q0 state at (x-1, y)
        LOADP_CG(qb,  g_q1[cur],   omy);   // q1 state at (x, y-1)

        // t-direction dual (periodic fwd diff) — overlaps halo-load latency
        float q2n[8];
#pragma unroll
        for (int t = 0; t < 8; t++) {
            float v = q2[t] + sig * (xb[(t + 1) & 7] - xb[t]);
            q2n[t] = fminf(fmaxf(v, -lam[t]), lam[t]);
        }

#pragma unroll
        for (int t = 0; t < 8; t++) {
            float pn = (pv[t] + sig * (xb[t] - xn[t])) * i1s;

            float v0  = q0[t] + sig * (bpx[t] - xb[t]);
            float q0n = fminf(fmaxf(v0, -lam[t]), lam[t]);
            float v1  = q1[t] + sig * (bpy[t] - xb[t]);
            float q1n = fminf(fmaxf(v1, -lam[t]), lam[t]);

            // redundant recompute of neighbor duals for the divergence
            float v0m = qa[t] + sig * (xb[t] - bmx[t]);
            float q0m = fminf(fmaxf(v0m, -lmx[t]), lmx[t]);
            float v1m = qb[t] + sig * (xb[t] - bmy[t]);
            float q1m = fminf(fmaxf(v1m, -lmy[t]), lmy[t]);

            float dv = (q0m - q0n) + (q1m - q1n)
                     + (q2n[(t + 7) & 7] - q2n[t]);

            float x1  = x0[t] - tauv * (pn + dv);
            float xbn = x1 + th * (x1 - x0[t]);

            x0[t] = x1; pv[t] = pn; q0[t] = q0n; q1[t] = q1n; xb[t] = xbn;
        }
#pragma unroll
        for (int t = 0; t < 8; t++) q2[t] = q2n[t];

        if (it != T - 1) {
            STOREP(g_xbar[nxt], o, xb);
            STOREP(g_q0[nxt],   o, q0);
            STOREP(g_q1[nxt],   o, q1);
            grid_barrier(it + 2);
        }
    }

    // ---- output ----
    STOREP(out, o, x0);

    // ---- self-reset counters for the next (graph-replayed) run ----
    // Safe: passing the final barrier proves ALL leaf+root arrivals for the
    // last epoch completed; nobody touches counters after that point.
    if (blockIdx.x == 0 && threadIdx.x == 0) {
#pragma unroll
        for (int i = 0; i < NLEAF; i++) st_release_gpu(&g_leaf[i * 32], 0u);
        st_release_gpu(&g_root, 0u);
    }
}

extern "C" void kernel_launch(void* const* d_in, const int* in_sizes, int n_in,
                              void* d_out, int out_size) {
    const float* x    = (const float*)d_in[0];
    const float* lam  = (const float*)d_in[1];
    const float* tau  = (const float*)d_in[2];
    const float* sigm = (const float*)d_in[3];
    const float* thet = (const float*)d_in[4];
    const int*   Tp   = (const int*)d_in[5];
    float* out = (float*)d_out;
    pdhg_persist_kernel<<<NCTA, NTHR>>>(x, lam, tau, sigm, thet, Tp, out);
}

// round 7
// speedup vs baseline: 3.5443x; 1.2001x over previous
#include <cuda_runtime.h>
#include <math.h>

// PDHG / Chambolle-Pock TV denoising, persistent-kernel, NEIGHBOR-SYNC version.
// P=2, C=1, NX=128, NY=128, NT=8; T=128 iterations.
// One thread per (p,x,y) pencil of NT=8 t-values.
// Registers: x0, p, q0, q1, q2 (own duals), q0m, q1m (minus-neighbor duals,
// carried via the same clip recurrence -> q0/q1 never published), xn, lam.
// Only xbar is published (double-buffered) for halo exchange.
// Sync: per-CTA release flags; each CTA waits ONLY on its 4 tile neighbors
// (wavefront pipelining -- no global barrier, skew amortizes instead of
// re-collapsing 128 times).

#define NXD 128
#define NYD 128
#define NTD 8
#define NPB 2
#define NPIX (NPB * NXD * NYD * NTD)   // 262144
#define NCTA 128
#define NTHR 256

__device__ __align__(256) float g_xbar[2][NPIX];
__device__ __align__(128) unsigned g_flags[NCTA * 32];   // 1 flag / 128B line

// ---- memory-model primitives ----
__device__ __forceinline__ void st_release_gpu(unsigned* p, unsigned v) {
    asm volatile("st.release.gpu.global.u32 [%0], %1;" :: "l"(p), "r"(v) : "memory");
}
__device__ __forceinline__ unsigned ld_acquire_gpu(const unsigned* p) {
    unsigned v;
    asm volatile("ld.acquire.gpu.global.u32 %0, [%1];" : "=r"(v) : "l"(p) : "memory");
    return v;
}

// Halo loads: L2-only (.cg) -> never sees stale L1.
#define LOADP_CG(dst, ptr, off) do { \
    float4 a_ = __ldcg(reinterpret_cast<const float4*>((ptr) + (off))); \
    float4 b_ = __ldcg(reinterpret_cast<const float4*>((ptr) + (off) + 4)); \
    dst[0]=a_.x; dst[1]=a_.y; dst[2]=a_.z; dst[3]=a_.w; \
    dst[4]=b_.x; dst[5]=b_.y; dst[6]=b_.z; dst[7]=b_.w; } while(0)

#define LOADP(dst, ptr, off) do { \
    float4 a_ = *reinterpret_cast<const float4*>((ptr) + (off)); \
    float4 b_ = *reinterpret_cast<const float4*>((ptr) + (off) + 4); \
    dst[0]=a_.x; dst[1]=a_.y; dst[2]=a_.z; dst[3]=a_.w; \
    dst[4]=b_.x; dst[5]=b_.y; dst[6]=b_.z; dst[7]=b_.w; } while(0)

#define STOREP(ptr, off, src) do { \
    *reinterpret_cast<float4*>((ptr) + (off))     = make_float4(src[0],src[1],src[2],src[3]); \
    *reinterpret_cast<float4*>((ptr) + (off) + 4) = make_float4(src[4],src[5],src[6],src[7]); } while(0)

extern "C" __global__ void __launch_bounds__(NTHR, 1)
pdhg_persist_kernel(const float* __restrict__ xin,
                    const float* __restrict__ lamin,
                    const float* __restrict__ taup,
                    const float* __restrict__ sigp,
                    const float* __restrict__ thp,
                    const int*   __restrict__ Tp,
                    float* __restrict__ out)
{
    // ---- scalars ----
    const float L    = sqrtf(13.0f);
    const float sig  = (1.0f / (1.0f + expf(-sigp[0]))) / L;
    const float tauv = (1.0f / (1.0f + expf(-taup[0]))) / L;
    const float th   = 1.0f / (1.0f + expf(-thp[0]));
    const float i1s  = 1.0f / (1.0f + sig);

    int T = Tp[0];
    if (T < 1 || T > 65536) {
        float tf = __int_as_float(T);
        T = (int)tf;
        if (T < 1 || T > 65536) T = 128;
    }

    // ---- thread -> pencil mapping: CTA = 16x16 (x,y) tile ----
    const int cta  = blockIdx.x;          // 0..127
    const int pp   = cta >> 6;            // batch 0..1
    const int tile = cta & 63;            // 8x8 tiles of 16x16
    const int tx   = tile >> 3, ty = tile & 7;
    const int x = (tx << 4) + (threadIdx.x >> 4);
    const int y = (ty << 4) + (threadIdx.x & 15);
    const int xp = (x + 1) & 127, xm = (x - 1) & 127;
    const int yp = (y + 1) & 127, ym = (y - 1) & 127;

    const int pb  = pp << 14;
    const int o   = (pb + (x  << 7) + y ) << 3;
    const int opx = (pb + (xp << 7) + y ) << 3;
    const int omx = (pb + (xm << 7) + y ) << 3;
    const int opy = (pb + (x  << 7) + yp) << 3;
    const int omy = (pb + (x  << 7) + ym) << 3;

    // ---- neighbor flag for THIS lane (lanes 0-3 poll one neighbor each) ----
    // Flags are monotonic across graph replays; every run advances every flag
    // by exactly T, so all flags are equal at run entry. base = own flag
    // (written only by this CTA -> race-free read). Wrap-safe unsigned diff.
    const unsigned base = ld_acquire_gpu(&g_flags[cta * 32]);
    const unsigned* nbr_flag = nullptr;
    {
        int txp = (tx + 1) & 7, txm = (tx - 1) & 7;
        int typ = (ty + 1) & 7, tym = (ty - 1) & 7;
        int nid = (threadIdx.x == 0) ? ((pp << 6) + (txp << 3) + ty)
                : (threadIdx.x == 1) ? ((pp << 6) + (txm << 3) + ty)
                : (threadIdx.x == 2) ? ((pp << 6) + (tx  << 3) + typ)
                :                      ((pp << 6) + (tx  << 3) + tym);
        nbr_flag = &g_flags[nid * 32];
    }

    // ---- persistent register state ----
    float xn[8], x0[8], pv[8], q0[8], q1[8], q2[8], xb[8], lam[8], lmx[8], lmy[8];
    float q0m[8], q1m[8];     // duals of (x-1,y) and (x,y-1), carried locally
    LOADP(xn,  xin,   o);
    LOADP(lam, lamin, o);
    LOADP(lmx, lamin, omx);
    LOADP(lmy, lamin, omy);
#pragma unroll
    for (int t = 0; t < 8; t++) {
        x0[t] = xn[t]; pv[t] = xn[t]; xb[t] = xn[t];
        q0[t] = 0.0f;  q1[t] = 0.0f;  q2[t] = 0.0f;
        q0m[t] = 0.0f; q1m[t] = 0.0f;
    }

    // init publish: xbar_0 into buffer 0, then flag = base+1
    STOREP(g_xbar[0], o, xb);
    __syncthreads();
    if (threadIdx.x == 0) st_release_gpu(&g_flags[cta * 32], base + 1u);

    // ---- main PDHG loop ----
    for (int it = 0; it < T; ++it) {
        const int cur = it & 1;
        const int nxt = cur ^ 1;

        // Wait for the 4 tile neighbors to have published epoch it+1.
        // This ALSO proves write-safety for buffer `nxt` below: flag >= it+1
        // means the neighbor finished iteration it-1, the last consumer of the
        // publish currently sitting in buffer `nxt` (publish `it`).
        if (threadIdx.x < 4) {
            const unsigned need = it + 1u;
            while (ld_acquire_gpu(nbr_flag) - base < need) { }
        }
        __syncthreads();

        // halo loads (only xbar), .cg = fresh from L2
        float bpx[8], bmx[8], bpy[8], bmy[8];
        LOADP_CG(bpx, g_xbar[cur], opx);
        LOADP_CG(bmx, g_xbar[cur], omx);
        LOADP_CG(bpy, g_xbar[cur], opy);
        LOADP_CG(bmy, g_xbar[cur], omy);

        // t-direction dual (periodic fwd diff) — overlaps halo-load latency
        float q2n[8];
#pragma unroll
        for (int t = 0; t < 8; t++) {
            float v = q2[t] + sig * (xb[(t + 1) & 7] - xb[t]);
            q2n[t] = fminf(fmaxf(v, -lam[t]), lam[t]);
        }

#pragma unroll
        for (int t = 0; t < 8; t++) {
            float pn = (pv[t] + sig * (xb[t] - xn[t])) * i1s;

            // own duals (forward differences)
            float v0  = q0[t] + sig * (bpx[t] - xb[t]);
            float q0n = fminf(fmaxf(v0, -lam[t]), lam[t]);
            float v1  = q1[t] + sig * (bpy[t] - xb[t]);
            float q1n = fminf(fmaxf(v1, -lam[t]), lam[t]);

            // minus-neighbor duals: same recurrence, carried in registers
            float v0m = q0m[t] + sig * (xb[t] - bmx[t]);
            float q0mn = fminf(fmaxf(v0m, -lmx[t]), lmx[t]);
            float v1m = q1m[t] + sig * (xb[t] - bmy[t]);
            float q1mn = fminf(fmaxf(v1m, -lmy[t]), lmy[t]);

            float dv = (q0mn - q0n) + (q1mn - q1n)
                     + (q2n[(t + 7) & 7] - q2n[t]);

            float x1  = x0[t] - tauv * (pn + dv);
            float xbn = x1 + th * (x1 - x0[t]);

            x0[t] = x1; pv[t] = pn;
            q0[t] = q0n; q1[t] = q1n; q0m[t] = q0mn; q1m[t] = q1mn;
            xb[t] = xbn;
        }
#pragma unroll
        for (int t = 0; t < 8; t++) q2[t] = q2n[t];

        if (it != T - 1) {
            STOREP(g_xbar[nxt], o, xb);
            __syncthreads();
            if (threadIdx.x == 0)
                st_release_gpu(&g_flags[cta * 32], base + it + 2u);
        }
    }

    // ---- output ----
    STOREP(out, o, x0);
}

extern "C" void kernel_launch(void* const* d_in, const int* in_sizes, int n_in,
                              void* d_out, int out_size) {
    const float* x    = (const float*)d_in[0];
    const float* lam  = (const float*)d_in[1];
    const float* tau  = (const float*)d_in[2];
    const float* sigm = (const float*)d_in[3];
    const float* thet = (const float*)d_in[4];
    const int*   Tp   = (const int*)d_in[5];
    float* out = (float*)d_out;
    pdhg_persist_kernel<<<NCTA, NTHR>>>(x, lam, tau, sigm, thet, Tp, out);
}

// round 8
// speedup vs baseline: 5.9793x; 1.6870x over previous
#include <cuda_runtime.h>
#include <math.h>

// PDHG / Chambolle-Pock TV denoising, persistent kernel, SLAB decomposition.
// P=2, C=1, NX=128, NY=128, NT=8; T=128 iterations.
// CTA = slab of 2 x-rows x full 128 y (256 threads, 1 pencil/thread).
// y-halo: entirely intra-CTA via double-buffered SMEM (no global traffic).
// x-halo: ONE remote pencil per thread; only 2 neighbor slabs -> 2 flags.
// Own duals q0,q1,q2 and minus-neighbor duals q0m,q1m carried in registers
// (clip recurrence) -> only xbar is ever published.

#define NXD 128
#define NYD 128
#define NTD 8
#define NPB 2
#define NPIX (NPB * NXD * NYD * NTD)   // 262144
#define NSLAB 64                        // slabs per batch (2 rows each)
#define NCTA (NSLAB * NPB)              // 128
#define NTHR 256

__device__ __align__(256) float g_xbar[2][NPIX];
__device__ __align__(128) unsigned g_flags[NCTA * 32];   // 1 flag / 128B line

// ---- memory-model primitives ----
__device__ __forceinline__ void st_release_gpu(unsigned* p, unsigned v) {
    asm volatile("st.release.gpu.global.u32 [%0], %1;" :: "l"(p), "r"(v) : "memory");
}
__device__ __forceinline__ unsigned ld_acquire_gpu(const unsigned* p) {
    unsigned v;
    asm volatile("ld.acquire.gpu.global.u32 %0, [%1];" : "=r"(v) : "l"(p) : "memory");
    return v;
}

#define LOADP_CG(dst, ptr, off) do { \
    float4 a_ = __ldcg(reinterpret_cast<const float4*>((ptr) + (off))); \
    float4 b_ = __ldcg(reinterpret_cast<const float4*>((ptr) + (off) + 4)); \
    dst[0]=a_.x; dst[1]=a_.y; dst[2]=a_.z; dst[3]=a_.w; \
    dst[4]=b_.x; dst[5]=b_.y; dst[6]=b_.z; dst[7]=b_.w; } while(0)

#define LOADP(dst, ptr, off) do { \
    float4 a_ = *reinterpret_cast<const float4*>((ptr) + (off)); \
    float4 b_ = *reinterpret_cast<const float4*>((ptr) + (off) + 4); \
    dst[0]=a_.x; dst[1]=a_.y; dst[2]=a_.z; dst[3]=a_.w; \
    dst[4]=b_.x; dst[5]=b_.y; dst[6]=b_.z; dst[7]=b_.w; } while(0)

#define STOREP(ptr, off, src) do { \
    *reinterpret_cast<float4*>((ptr) + (off))     = make_float4(src[0],src[1],src[2],src[3]); \
    *reinterpret_cast<float4*>((ptr) + (off) + 4) = make_float4(src[4],src[5],src[6],src[7]); } while(0)

#define LOADS(dst, smemrow) do { \
    float4 a_ = *reinterpret_cast<const float4*>(smemrow); \
    float4 b_ = *reinterpret_cast<const float4*>((smemrow) + 4); \
    dst[0]=a_.x; dst[1]=a_.y; dst[2]=a_.z; dst[3]=a_.w; \
    dst[4]=b_.x; dst[5]=b_.y; dst[6]=b_.z; dst[7]=b_.w; } while(0)

extern "C" __global__ void __launch_bounds__(NTHR, 1)
pdhg_persist_kernel(const float* __restrict__ xin,
                    const float* __restrict__ lamin,
                    const float* __restrict__ taup,
                    const float* __restrict__ sigp,
                    const float* __restrict__ thp,
                    const int*   __restrict__ Tp,
                    float* __restrict__ out)
{
    __shared__ float sm_xb[2][NTHR][NTD];   // 16 KB, double-buffered xbar

    // ---- scalars ----
    const float L    = sqrtf(13.0f);
    const float sig  = (1.0f / (1.0f + expf(-sigp[0]))) / L;
    const float tauv = (1.0f / (1.0f + expf(-taup[0]))) / L;
    const float th   = 1.0f / (1.0f + expf(-thp[0]));
    const float i1s  = 1.0f / (1.0f + sig);

    int T = Tp[0];
    if (T < 1 || T > 65536) {
        float tf = __int_as_float(T);
        T = (int)tf;
        if (T < 1 || T > 65536) T = 128;
    }

    // ---- mapping: cta -> (batch, slab); thread -> (row in slab, y) ----
    const int cta = blockIdx.x;           // 0..127
    const int pp  = cta >> 6;             // batch
    const int s   = cta & 63;             // slab (rows 2s, 2s+1)
    const int tid = threadIdx.x;
    const int r   = tid >> 7;             // 0 or 1
    const int y   = tid & 127;
    const int x   = (s << 1) + r;
    const int yp  = (y + 1) & 127, ym = (y - 1) & 127;

    const int pb = pp << 14;
    const int o  = (pb + (x << 7) + y) << 3;           // own pencil
    // the single remote pencil this thread needs:
    const int xr = (r == 0) ? ((x - 1) & 127) : ((x + 1) & 127);
    const int orem = (pb + (xr << 7) + y) << 3;
    // static lambda of minus-neighbors:
    const int omx = (pb + (((x - 1) & 127) << 7) + y) << 3;
    const int omy = (pb + (x << 7) + ym) << 3;

    // smem indices of intra-CTA neighbors
    const int partner = (r == 0) ? (128 + y) : y;      // other row, same y
    const int iyp = (r << 7) + yp;
    const int iym = (r << 7) + ym;

    // flag this thread's warp polls: slab s-1 for row0, slab s+1 for row1
    const unsigned* nbr_flag =
        &g_flags[((pp << 6) + ((r == 0) ? ((s + 63) & 63) : ((s + 1) & 63))) * 32];
    const unsigned base = ld_acquire_gpu(&g_flags[cta * 32]);

    // ---- persistent register state ----
    float xn[8], x0[8], pv[8], q0[8], q1[8], q2[8], xb[8], lam[8], lmx[8], lmy[8];
    float q0m[8], q1m[8];
    LOADP(xn,  xin,   o);
    LOADP(lam, lamin, o);
    LOADP(lmx, lamin, omx);
    LOADP(lmy, lamin, omy);
#pragma unroll
    for (int t = 0; t < 8; t++) {
        x0[t] = xn[t]; pv[t] = xn[t]; xb[t] = xn[t];
        q0[t] = 0.0f;  q1[t] = 0.0f;  q2[t] = 0.0f;
        q0m[t] = 0.0f; q1m[t] = 0.0f;
    }

    // init publish: xbar_0 -> global buffer 0 + smem buffer 0, then flag base+1
    STOREP(g_xbar[0], o, xb);
#pragma unroll
    for (int t = 0; t < 8; t++) sm_xb[0][tid][t] = xb[t];
    __syncthreads();
    if (tid == 0) st_release_gpu(&g_flags[cta * 32], base + 1u);

    // ---- main loop ----
    for (int it = 0; it < T; ++it) {
        const int cur = it & 1;
        const int nxt = cur ^ 1;

        // per-warp wait: lane 0 polls the one neighbor flag this warp needs,
        // then syncwarp releases the warp (no CTA-wide pre-barrier).
        // flag >= it+1 also proves write-safety of buffer nxt (see R7 proof).
        if ((tid & 31) == 0) {
            const unsigned need = it + 1u;
            while (ld_acquire_gpu(nbr_flag) - base < need) { }
        }
        __syncwarp();

        // ONE remote pencil (bmx for row0, bpx for row1), L2-fresh
        float rem[8];
        LOADP_CG(rem, g_xbar[cur], orem);

        // intra-CTA halos from smem (written last iteration, barrier'd)
        float prt[8], bpy[8], bmy[8];
        LOADS(prt, &sm_xb[cur][partner][0]);
        LOADS(bpy, &sm_xb[cur][iyp][0]);
        LOADS(bmy, &sm_xb[cur][iym][0]);

        const float* bpx = (r == 0) ? prt : rem;
        const float* bmx = (r == 0) ? rem : prt;

        // t-direction dual (periodic fwd diff)
        float q2n[8];
#pragma unroll
        for (int t = 0; t < 8; t++) {
            float v = q2[t] + sig * (xb[(t + 1) & 7] - xb[t]);
            q2n[t] = fminf(fmaxf(v, -lam[t]), lam[t]);
        }

#pragma unroll
        for (int t = 0; t < 8; t++) {
            float pn = (pv[t] + sig * (xb[t] - xn[t])) * i1s;

            float v0  = q0[t] + sig * (bpx[t] - xb[t]);
            float q0n = fminf(fmaxf(v0, -lam[t]), lam[t]);
            float v1  = q1[t] + sig * (bpy[t] - xb[t]);
            float q1n = fminf(fmaxf(v1, -lam[t]), lam[t]);

            float v0m  = q0m[t] + sig * (xb[t] - bmx[t]);
            float q0mn = fminf(fmaxf(v0m, -lmx[t]), lmx[t]);
            float v1m  = q1m[t] + sig * (xb[t] - bmy[t]);
            float q1mn = fminf(fmaxf(v1m, -lmy[t]), lmy[t]);

            float dv = (q0mn - q0n) + (q1mn - q1n)
                     + (q2n[(t + 7) & 7] - q2n[t]);

            float x1  = x0[t] - tauv * (pn + dv);
            float xbn = x1 + th * (x1 - x0[t]);

            x0[t] = x1; pv[t] = pn;
            q0[t] = q0n; q1[t] = q1n; q0m[t] = q0mn; q1m[t] = q1mn;
            xb[t] = xbn;
        }
#pragma unroll
        for (int t = 0; t < 8; t++) q2[t] = q2n[t];

        if (it != T - 1) {
            STOREP(g_xbar[nxt], o, xb);            // publish for x-neighbors
#pragma unroll
            for (int t = 0; t < 8; t++) sm_xb[nxt][tid][t] = xb[t];
            __syncthreads();                        // one barrier per iter
            if (tid == 0)
                st_release_gpu(&g_flags[cta * 32], base + it + 2u);
        }
    }

    // ---- output ----
    STOREP(out, o, x0);
}

extern "C" void kernel_launch(void* const* d_in, const int* in_sizes, int n_in,
                              void* d_out, int out_size) {
    const float* x    = (const float*)d_in[0];
    const float* lam  = (const float*)d_in[1];
    const float* tau  = (const float*)d_in[2];
    const float* sigm = (const float*)d_in[3];
    const float* thet = (const float*)d_in[4];
    const int*   Tp   = (const int*)d_in[5];
    float* out = (float*)d_out;
    pdhg_persist_kernel<<<NCTA, NTHR>>>(x, lam, tau, sigm, thet, Tp, out);
}